// round 1
// baseline (speedup 1.0000x reference)
#include <cuda_runtime.h>
#include <math.h>

#define B_ 4
#define N_ 2048
#define C_ 1024
#define H_ 16
#define D_ 64
#define BH_ (B_*H_)

// Scratch (allocation-free rule: static device globals)
__device__ float g_q[(size_t)BH_*N_*D_];     // [B,H,N,D]
__device__ float g_k[(size_t)BH_*N_*D_];
__device__ float g_v[(size_t)BH_*N_*D_];
__device__ float g_att[(size_t)B_*N_*C_];    // [B,N,C] attention output

// ---------------------------------------------------------------------------
// Kernel 1: QKV projection. x[8192,1024] @ W[1024,3072], scattered to q/k/v.
// 64x64 block tile, 256 threads, 4x4 per-thread micro-tile, K-tile 16.
// ---------------------------------------------------------------------------
__global__ __launch_bounds__(256) void qkv_gemm_kernel(
    const float* __restrict__ x, const float* __restrict__ W)
{
    const int K  = C_;        // 1024
    const int Nw = 3 * C_;    // 3072
    __shared__ float At[16][64];   // A transposed: At[k][row]
    __shared__ float Bs[16][64];   // Bs[k][col]

    int tid = threadIdx.x;
    int ty = tid >> 4, tx = tid & 15;
    int row0 = blockIdx.y * 64;
    int col0 = blockIdx.x * 64;

    int arow = tid >> 2,  ak  = (tid & 3) * 4;    // A: 64 rows x 4 float4
    int brow = tid >> 4,  bcol = (tid & 15) * 4;  // B: 16 rows x 16 float4

    float acc[4][4] = {};

    for (int k0 = 0; k0 < K; k0 += 16) {
        float4 a = *(const float4*)&x[(size_t)(row0 + arow) * K + k0 + ak];
        At[ak + 0][arow] = a.x; At[ak + 1][arow] = a.y;
        At[ak + 2][arow] = a.z; At[ak + 3][arow] = a.w;
        *(float4*)&Bs[brow][bcol] =
            *(const float4*)&W[(size_t)(k0 + brow) * Nw + col0 + bcol];
        __syncthreads();
        #pragma unroll
        for (int kk = 0; kk < 16; kk++) {
            float4 av = *(float4*)&At[kk][ty * 4];
            float4 bv = *(float4*)&Bs[kk][tx * 4];
            float ar[4] = {av.x, av.y, av.z, av.w};
            float br[4] = {bv.x, bv.y, bv.z, bv.w};
            #pragma unroll
            for (int i = 0; i < 4; i++)
                #pragma unroll
                for (int j = 0; j < 4; j++)
                    acc[i][j] = fmaf(ar[i], br[j], acc[i][j]);
        }
        __syncthreads();
    }

    // Scatter: whole block tile lies in one (which, h, b) since 64 | boundaries
    int which = col0 >> 10;                 // 0=q, 1=k, 2=v
    int h     = (col0 & 1023) >> 6;
    int b     = row0 >> 11;
    int n0    = row0 & (N_ - 1);
    float* dst = (which == 0) ? g_q : ((which == 1) ? g_k : g_v);
    size_t base = ((size_t)(b * H_ + h)) * N_ * D_;
    #pragma unroll
    for (int i = 0; i < 4; i++) {
        int n = n0 + ty * 4 + i;
        float4 val = make_float4(acc[i][0], acc[i][1], acc[i][2], acc[i][3]);
        *(float4*)&dst[base + (size_t)n * D_ + tx * 4] = val;
    }
}

// ---------------------------------------------------------------------------
// Kernel 2: flash attention (causal). One block per (bh, 64-row q tile).
// 256 threads, 4x4 micro-tiles, online softmax in registers.
// Smem: Qt[d][r] 16KB + Kt[d][c]/Ps[r][c] 16KB (reused) + Vs[c][d] 16KB = 48KB.
// ---------------------------------------------------------------------------
__global__ __launch_bounds__(256) void attn_kernel()
{
    __shared__ float Qt[64 * 64];   // transposed [d][r]
    __shared__ float Kt[64 * 64];   // transposed [d][c]; reused as Ps[r][c]
    __shared__ float Vs[64 * 64];   // natural    [c][d]

    int tid = threadIdx.x;
    int ty = tid >> 4, tx = tid & 15;
    int qt = blockIdx.x;
    int bh = blockIdx.y;
    int q0 = qt * 64;

    const float* Qg = g_q + (size_t)bh * N_ * D_;
    const float* Kg = g_k + (size_t)bh * N_ * D_;
    const float* Vg = g_v + (size_t)bh * N_ * D_;

    // Load Q tile transposed (persists for all key tiles)
    #pragma unroll
    for (int it = 0; it < 4; ++it) {
        int v = tid + 256 * it;
        int r = v >> 4, d4 = (v & 15) * 4;
        float4 q = *(const float4*)&Qg[(size_t)(q0 + r) * D_ + d4];
        Qt[(d4 + 0) * 64 + r] = q.x; Qt[(d4 + 1) * 64 + r] = q.y;
        Qt[(d4 + 2) * 64 + r] = q.z; Qt[(d4 + 3) * 64 + r] = q.w;
    }

    float m[4], l[4], o[4][4];
    #pragma unroll
    for (int i = 0; i < 4; i++) {
        m[i] = -1e30f; l[i] = 0.0f;
        #pragma unroll
        for (int j = 0; j < 4; j++) o[i][j] = 0.0f;
    }

    for (int jt = 0; jt <= qt; ++jt) {
        int k0 = jt * 64;
        __syncthreads();   // prior PV reads done before overwriting Kt/Vs
        #pragma unroll
        for (int it = 0; it < 4; ++it) {
            int v = tid + 256 * it;
            int r = v >> 4, d4 = (v & 15) * 4;
            float4 kv = *(const float4*)&Kg[(size_t)(k0 + r) * D_ + d4];
            Kt[(d4 + 0) * 64 + r] = kv.x; Kt[(d4 + 1) * 64 + r] = kv.y;
            Kt[(d4 + 2) * 64 + r] = kv.z; Kt[(d4 + 3) * 64 + r] = kv.w;
            float4 vv = *(const float4*)&Vg[(size_t)(k0 + r) * D_ + d4];
            *(float4*)&Vs[r * 64 + d4] = vv;
        }
        __syncthreads();

        // S = Q K^T (per-thread 4x4)
        float s[4][4] = {};
        #pragma unroll 4
        for (int d = 0; d < 64; d++) {
            float4 av = *(float4*)&Qt[d * 64 + ty * 4];
            float4 bv = *(float4*)&Kt[d * 64 + tx * 4];
            float ar[4] = {av.x, av.y, av.z, av.w};
            float br[4] = {bv.x, bv.y, bv.z, bv.w};
            #pragma unroll
            for (int i = 0; i < 4; i++)
                #pragma unroll
                for (int j = 0; j < 4; j++)
                    s[i][j] = fmaf(ar[i], br[j], s[i][j]);
        }

        // scale + causal mask (only the diagonal tile needs masking)
        #pragma unroll
        for (int i = 0; i < 4; i++)
            #pragma unroll
            for (int j = 0; j < 4; j++) {
                s[i][j] *= 0.125f;   // 1/sqrt(64)
                if (jt == qt && (tx * 4 + j) > (ty * 4 + i)) s[i][j] = -1e30f;
            }

        // online softmax: row max/sum across the 16 tx lanes (shuffle reduce)
        #pragma unroll
        for (int i = 0; i < 4; i++) {
            float rm = fmaxf(fmaxf(s[i][0], s[i][1]), fmaxf(s[i][2], s[i][3]));
            #pragma unroll
            for (int off = 1; off < 16; off <<= 1)
                rm = fmaxf(rm, __shfl_xor_sync(0xffffffffu, rm, off));
            float mn = fmaxf(m[i], rm);
            float alpha = __expf(m[i] - mn);
            float rs = 0.0f;
            #pragma unroll
            for (int j = 0; j < 4; j++) {
                s[i][j] = __expf(s[i][j] - mn);
                rs += s[i][j];
            }
            #pragma unroll
            for (int off = 1; off < 16; off <<= 1)
                rs += __shfl_xor_sync(0xffffffffu, rs, off);
            l[i] = l[i] * alpha + rs;
            m[i] = mn;
            #pragma unroll
            for (int j = 0; j < 4; j++) o[i][j] *= alpha;
        }

        __syncthreads();   // everyone done reading Kt before P overwrite
        #pragma unroll
        for (int i = 0; i < 4; i++)
            *(float4*)&Kt[(ty * 4 + i) * 64 + tx * 4] =
                make_float4(s[i][0], s[i][1], s[i][2], s[i][3]);
        __syncthreads();

        // O += P @ V  (P in Kt as [r][c], V natural [c][d])
        #pragma unroll 2
        for (int c4 = 0; c4 < 64; c4 += 4) {
            float pr[4][4];
            #pragma unroll
            for (int i = 0; i < 4; i++) {
                float4 p4 = *(float4*)&Kt[(ty * 4 + i) * 64 + c4];
                pr[i][0] = p4.x; pr[i][1] = p4.y; pr[i][2] = p4.z; pr[i][3] = p4.w;
            }
            #pragma unroll
            for (int cc = 0; cc < 4; cc++) {
                float4 bv = *(float4*)&Vs[(c4 + cc) * 64 + tx * 4];
                float br[4] = {bv.x, bv.y, bv.z, bv.w};
                #pragma unroll
                for (int i = 0; i < 4; i++)
                    #pragma unroll
                    for (int j = 0; j < 4; j++)
                        o[i][j] = fmaf(pr[i][cc], br[j], o[i][j]);
            }
        }
    }

    // epilogue: O / l -> g_att [b][n][h*64 + d]
    int b = bh >> 4, h = bh & 15;
    #pragma unroll
    for (int i = 0; i < 4; i++) {
        int n = q0 + ty * 4 + i;
        float inv = 1.0f / l[i];
        float4 val = make_float4(o[i][0] * inv, o[i][1] * inv,
                                 o[i][2] * inv, o[i][3] * inv);
        *(float4*)&g_att[((size_t)b * N_ + n) * C_ + h * 64 + tx * 4] = val;
    }
}

// ---------------------------------------------------------------------------
// Kernel 3: output projection. g_att[8192,1024] @ Wp[1024,1024] + bias -> out
// ---------------------------------------------------------------------------
__global__ __launch_bounds__(256) void proj_gemm_kernel(
    const float* __restrict__ W, const float* __restrict__ bias,
    float* __restrict__ out)
{
    const int K = C_, Nw = C_;
    __shared__ float At[16][64];
    __shared__ float Bs[16][64];

    int tid = threadIdx.x;
    int ty = tid >> 4, tx = tid & 15;
    int row0 = blockIdx.y * 64;
    int col0 = blockIdx.x * 64;

    int arow = tid >> 2,  ak  = (tid & 3) * 4;
    int brow = tid >> 4,  bcol = (tid & 15) * 4;

    float acc[4][4] = {};
    for (int k0 = 0; k0 < K; k0 += 16) {
        float4 a = *(const float4*)&g_att[(size_t)(row0 + arow) * K + k0 + ak];
        At[ak + 0][arow] = a.x; At[ak + 1][arow] = a.y;
        At[ak + 2][arow] = a.z; At[ak + 3][arow] = a.w;
        *(float4*)&Bs[brow][bcol] =
            *(const float4*)&W[(size_t)(k0 + brow) * Nw + col0 + bcol];
        __syncthreads();
        #pragma unroll
        for (int kk = 0; kk < 16; kk++) {
            float4 av = *(float4*)&At[kk][ty * 4];
            float4 bv = *(float4*)&Bs[kk][tx * 4];
            float ar[4] = {av.x, av.y, av.z, av.w};
            float br[4] = {bv.x, bv.y, bv.z, bv.w};
            #pragma unroll
            for (int i = 0; i < 4; i++)
                #pragma unroll
                for (int j = 0; j < 4; j++)
                    acc[i][j] = fmaf(ar[i], br[j], acc[i][j]);
        }
        __syncthreads();
    }

    float4 bv = *(const float4*)&bias[col0 + tx * 4];
    float bb[4] = {bv.x, bv.y, bv.z, bv.w};
    #pragma unroll
    for (int i = 0; i < 4; i++) {
        int r = row0 + ty * 4 + i;
        float4 val = make_float4(acc[i][0] + bb[0], acc[i][1] + bb[1],
                                 acc[i][2] + bb[2], acc[i][3] + bb[3]);
        *(float4*)&out[(size_t)r * Nw + col0 + tx * 4] = val;
    }
}

// ---------------------------------------------------------------------------
extern "C" void kernel_launch(void* const* d_in, const int* in_sizes, int n_in,
                              void* d_out, int out_size)
{
    const float* x     = (const float*)d_in[0];
    // d_in[1] = attn_mask: exact additive causal mask; handled analytically.
    const float* Wqkv  = (const float*)d_in[2];
    const float* Wproj = (const float*)d_in[3];
    const float* bproj = (const float*)d_in[4];
    float* out = (float*)d_out;

    dim3 g1(3 * C_ / 64, (B_ * N_) / 64);       // 48 x 128
    qkv_gemm_kernel<<<g1, 256>>>(x, Wqkv);

    dim3 g2(N_ / 64, BH_);                       // 32 x 64
    attn_kernel<<<g2, 256>>>();

    dim3 g3(C_ / 64, (B_ * N_) / 64);            // 16 x 128
    proj_gemm_kernel<<<g3, 256>>>(Wproj, bproj, out);
}

// round 11
// speedup vs baseline: 1.5776x; 1.5776x over previous
#include <cuda_runtime.h>
#include <cuda_bf16.h>
#include <cstdint>
#include <math.h>

#define B_ 4
#define N_ 2048
#define C_ 1024
#define H_ 16
#define D_ 64
#define BH_ (B_*H_)

// ---------------- device scratch (allocation-free rule) ----------------
__device__ float g_q[(size_t)BH_*N_*D_];
__device__ float g_k[(size_t)BH_*N_*D_];
__device__ float g_v[(size_t)BH_*N_*D_];
__device__ __nv_bfloat16 g_xh[(size_t)B_*N_*C_];
__device__ __nv_bfloat16 g_xl[(size_t)B_*N_*C_];
__device__ __nv_bfloat16 g_wqh[(size_t)3*C_*C_];   // W_qkv^T [3072][1024]
__device__ __nv_bfloat16 g_wql[(size_t)3*C_*C_];
__device__ __nv_bfloat16 g_wph[(size_t)C_*C_];     // W_proj^T [1024][1024]
__device__ __nv_bfloat16 g_wpl[(size_t)C_*C_];
__device__ __nv_bfloat16 g_atth[(size_t)B_*N_*C_];
__device__ __nv_bfloat16 g_attl[(size_t)B_*N_*C_];

// ---------------- helpers ----------------
__device__ __forceinline__ uint32_t smem_u32(const void* p) {
    uint32_t a;
    asm("{ .reg .u64 t; cvta.to.shared.u64 t, %1; cvt.u32.u64 %0, t; }"
        : "=r"(a) : "l"(p));
    return a;
}
#define CPA(dst, src) \
    asm volatile("cp.async.cg.shared.global [%0], [%1], 16;" \
                 :: "r"(dst), "l"(src) : "memory")
#define CP_COMMIT() asm volatile("cp.async.commit_group;" ::: "memory")
#define CP_WAIT0()  asm volatile("cp.async.wait_group 0;" ::: "memory")

__device__ __forceinline__ void ldsm4(uint32_t* r, uint32_t addr) {
    asm volatile("ldmatrix.sync.aligned.m8n8.x4.shared.b16 {%0,%1,%2,%3}, [%4];"
                 : "=r"(r[0]), "=r"(r[1]), "=r"(r[2]), "=r"(r[3]) : "r"(addr));
}
__device__ __forceinline__ void mma16816(float* d, const uint32_t* a,
                                         uint32_t b0, uint32_t b1) {
    asm volatile(
        "mma.sync.aligned.m16n8k16.row.col.f32.bf16.bf16.f32 "
        "{%0,%1,%2,%3}, {%4,%5,%6,%7}, {%8,%9}, {%0,%1,%2,%3};"
        : "+f"(d[0]), "+f"(d[1]), "+f"(d[2]), "+f"(d[3])
        : "r"(a[0]), "r"(a[1]), "r"(a[2]), "r"(a[3]), "r"(b0), "r"(b1));
}

// smem: 2 stages x 4 tiles (Ah, Al, Bh, Bl), each 128 rows x 128B, SW128
#define SOFF(s, w) (((s)*4 + (w)) * 16384)
#define SMEM_DYN (8 * 16384)

// ---------------------------------------------------------------------------
// HMMA split-3 mainloop: acc += AhBh + AhBl + AlBh over K=1024
// CTA tile 128x128, 8 warps (2 m x 4 n), per-warp 64x32, K-chunk 64.
// ---------------------------------------------------------------------------
__device__ __forceinline__ void hmma_tile(
    const __nv_bfloat16* __restrict__ Ah, const __nv_bfloat16* __restrict__ Al,
    const __nv_bfloat16* __restrict__ Bh, const __nv_bfloat16* __restrict__ Bl,
    int m0, int n0, char* smem, float acc[4][4][4])
{
    const int NC = 16;                       // 1024 / 64
    uint32_t sb = smem_u32(smem);
    int tid = threadIdx.x, lane = tid & 31;
    int wm = (tid >> 5) & 1, wn = tid >> 6;

    // staging map: e -> row (0..127), 16B slot (0..7), swizzled offset
    int rr[4]; int koB[4]; uint32_t soff[4];
    #pragma unroll
    for (int i = 0; i < 4; i++) {
        int e = tid + 256 * i;
        rr[i] = e >> 3; koB[i] = (e & 7) * 16;
        soff[i] = (uint32_t)(rr[i] * 128 + (koB[i] ^ ((rr[i] & 7) << 4)));
    }

    // ldmatrix address components
    int lr = lane & 15;
    uint32_t ch16 = (uint32_t)((lane >> 4) * 16);
    uint32_t arow[4], xa[4], brow[2], xb[2];
    #pragma unroll
    for (int mt = 0; mt < 4; mt++) {
        int r = wm * 64 + mt * 16 + lr;
        arow[mt] = (uint32_t)(r * 128); xa[mt] = (uint32_t)((r & 7) << 4);
    }
    #pragma unroll
    for (int p = 0; p < 2; p++) {
        int r = wn * 32 + p * 16 + lr;
        brow[p] = (uint32_t)(r * 128); xb[p] = (uint32_t)((r & 7) << 4);
    }

    #define STAGE(c, s) {                                                      \
        int k0b = (c) * 128;                                                   \
        _Pragma("unroll") for (int i = 0; i < 4; i++) {                        \
            const char* asrc = (const char*)Ah + (size_t)(m0 + rr[i])*2048 + k0b + koB[i]; \
            const char* lsrc = (const char*)Al + (size_t)(m0 + rr[i])*2048 + k0b + koB[i]; \
            const char* bsrc = (const char*)Bh + (size_t)(n0 + rr[i])*2048 + k0b + koB[i]; \
            const char* csrc = (const char*)Bl + (size_t)(n0 + rr[i])*2048 + k0b + koB[i]; \
            CPA(sb + SOFF(s,0) + soff[i], asrc);                               \
            CPA(sb + SOFF(s,1) + soff[i], lsrc);                               \
            CPA(sb + SOFF(s,2) + soff[i], bsrc);                               \
            CPA(sb + SOFF(s,3) + soff[i], csrc); } }

    STAGE(0, 0); CP_COMMIT(); CP_WAIT0();
    __syncthreads();

    for (int c = 0; c < NC; c++) {
        int s = c & 1;
        if (c + 1 < NC) { STAGE(c + 1, (c + 1) & 1); CP_COMMIT(); }

        uint32_t bAh = sb + SOFF(s, 0), bAl = sb + SOFF(s, 1);
        uint32_t bBh = sb + SOFF(s, 2), bBl = sb + SOFF(s, 3);
        #pragma unroll
        for (int ks = 0; ks < 4; ks++) {
            uint32_t ka = (uint32_t)(ks * 32) + ch16;
            uint32_t fah[4][4], fal[4][4], fbh[2][4], fbl[2][4];
            #pragma unroll
            for (int mt = 0; mt < 4; mt++) {
                ldsm4(fah[mt], bAh + arow[mt] + (ka ^ xa[mt]));
                ldsm4(fal[mt], bAl + arow[mt] + (ka ^ xa[mt]));
            }
            #pragma unroll
            for (int p = 0; p < 2; p++) {
                ldsm4(fbh[p], bBh + brow[p] + (ka ^ xb[p]));
                ldsm4(fbl[p], bBl + brow[p] + (ka ^ xb[p]));
            }
            #pragma unroll
            for (int mt = 0; mt < 4; mt++)
                #pragma unroll
                for (int nt = 0; nt < 4; nt++) {
                    int p = nt >> 1, o = nt & 1;
                    mma16816(acc[mt][nt], fah[mt], fbh[p][o], fbh[p][o + 2]);
                    mma16816(acc[mt][nt], fah[mt], fbl[p][o], fbl[p][o + 2]);
                    mma16816(acc[mt][nt], fal[mt], fbh[p][o], fbh[p][o + 2]);
                }
        }
        if (c + 1 < NC) CP_WAIT0();
        __syncthreads();
    }
    #undef STAGE
}

// ---------------------------------------------------------------------------
// QKV GEMM -> scatter fp32 to g_q/g_k/g_v [B,H,N,D]
// ---------------------------------------------------------------------------
__global__ __launch_bounds__(256, 1) void hmma_qkv_kernel() {
    extern __shared__ char dsm[];
    int m0 = blockIdx.y * 128, n0 = blockIdx.x * 128;
    float acc[4][4][4] = {};
    hmma_tile(g_xh, g_xl, g_wqh, g_wql, m0, n0, dsm, acc);

    int lane = threadIdx.x & 31;
    int wm = (threadIdx.x >> 5) & 1, wn = threadIdx.x >> 6;
    int g = lane >> 2, tg = lane & 3;
    #pragma unroll
    for (int mt = 0; mt < 4; mt++)
        #pragma unroll
        for (int nt = 0; nt < 4; nt++) {
            int m = m0 + wm * 64 + mt * 16 + g;
            int n = n0 + wn * 32 + nt * 8 + tg * 2;
            int which = n >> 10, h = (n >> 6) & 15, d = n & 63;
            float* dst = (which == 0) ? g_q : ((which == 1) ? g_k : g_v);
            int b = m >> 11, nn = m & (N_ - 1);
            size_t base = (((size_t)(b * H_ + h)) * N_ + nn) * D_ + d;
            *(float2*)&dst[base] = make_float2(acc[mt][nt][0], acc[mt][nt][1]);
            *(float2*)&dst[base + 8 * D_] = make_float2(acc[mt][nt][2], acc[mt][nt][3]);
        }
}

// ---------------------------------------------------------------------------
// proj GEMM + bias -> out
// ---------------------------------------------------------------------------
__global__ __launch_bounds__(256, 1) void hmma_proj_kernel(
    const float* __restrict__ bias, float* __restrict__ out) {
    extern __shared__ char dsm[];
    int m0 = blockIdx.y * 128, n0 = blockIdx.x * 128;
    float acc[4][4][4] = {};
    hmma_tile(g_atth, g_attl, g_wph, g_wpl, m0, n0, dsm, acc);

    int lane = threadIdx.x & 31;
    int wm = (threadIdx.x >> 5) & 1, wn = threadIdx.x >> 6;
    int g = lane >> 2, tg = lane & 3;
    #pragma unroll
    for (int mt = 0; mt < 4; mt++)
        #pragma unroll
        for (int nt = 0; nt < 4; nt++) {
            int m = m0 + wm * 64 + mt * 16 + g;
            int n = n0 + wn * 32 + nt * 8 + tg * 2;
            float b0 = bias[n], b1 = bias[n + 1];
            *(float2*)&out[(size_t)m * C_ + n] =
                make_float2(acc[mt][nt][0] + b0, acc[mt][nt][1] + b1);
            *(float2*)&out[(size_t)(m + 8) * C_ + n] =
                make_float2(acc[mt][nt][2] + b0, acc[mt][nt][3] + b1);
        }
}

// ---------------------------------------------------------------------------
// Conversion kernels
// ---------------------------------------------------------------------------
__global__ __launch_bounds__(256) void conv_split_kernel(
    const float* __restrict__ in, __nv_bfloat16* __restrict__ oh,
    __nv_bfloat16* __restrict__ ol, int n4) {
    int i = blockIdx.x * 256 + threadIdx.x;
    if (i >= n4) return;
    float4 v = ((const float4*)in)[i];
    float vv[4] = {v.x, v.y, v.z, v.w};
    __nv_bfloat162 h2[2], l2[2];
    #pragma unroll
    for (int j = 0; j < 4; j++) {
        __nv_bfloat16 h = __float2bfloat16(vv[j]);
        __nv_bfloat16 l = __float2bfloat16(vv[j] - __bfloat162float(h));
        ((__nv_bfloat16*)h2)[j] = h;
        ((__nv_bfloat16*)l2)[j] = l;
    }
    ((__nv_bfloat162*)oh)[i*2]   = h2[0]; ((__nv_bfloat162*)oh)[i*2+1] = h2[1];
    ((__nv_bfloat162*)ol)[i*2]   = l2[0]; ((__nv_bfloat162*)ol)[i*2+1] = l2[1];
}

// W[K][Nw] -> out[Nw][K] transpose + split (32x32 tiles via smem)
__global__ __launch_bounds__(256) void conv_T_kernel(
    const float* __restrict__ W, __nv_bfloat16* __restrict__ oh,
    __nv_bfloat16* __restrict__ ol, int K, int Nw) {
    __shared__ float t[32][33];
    int n0 = blockIdx.x * 32, k0 = blockIdx.y * 32;
    int tx = threadIdx.x & 31, ty = threadIdx.x >> 5;   // 32 x 8
    #pragma unroll
    for (int p = 0; p < 32; p += 8)
        t[ty + p][tx] = W[(size_t)(k0 + ty + p)*Nw + n0 + tx];
    __syncthreads();
    #pragma unroll
    for (int p = 0; p < 32; p += 8) {
        float v = t[tx][ty + p];
        __nv_bfloat16 h = __float2bfloat16(v);
        __nv_bfloat16 l = __float2bfloat16(v - __bfloat162float(h));
        size_t o = (size_t)(n0 + ty + p)*K + k0 + tx;
        oh[o] = h; ol[o] = l;
    }
}

// ---------------------------------------------------------------------------
// Flash attention (SIMT, proven correct); epilogue emits bf16 split
// ---------------------------------------------------------------------------
__global__ __launch_bounds__(256) void attn_kernel() {
    __shared__ float Qt[64 * 64];
    __shared__ float Kt[64 * 64];
    __shared__ float Vs[64 * 64];

    int tid = threadIdx.x;
    int ty = tid >> 4, tx = tid & 15;
    int qt = blockIdx.x, bh = blockIdx.y;
    int q0 = qt * 64;

    const float* Qg = g_q + (size_t)bh * N_ * D_;
    const float* Kg = g_k + (size_t)bh * N_ * D_;
    const float* Vg = g_v + (size_t)bh * N_ * D_;

    #pragma unroll
    for (int it = 0; it < 4; ++it) {
        int v = tid + 256 * it;
        int r = v >> 4, d4 = (v & 15) * 4;
        float4 q = *(const float4*)&Qg[(size_t)(q0 + r) * D_ + d4];
        Qt[(d4 + 0) * 64 + r] = q.x; Qt[(d4 + 1) * 64 + r] = q.y;
        Qt[(d4 + 2) * 64 + r] = q.z; Qt[(d4 + 3) * 64 + r] = q.w;
    }

    float m[4], l[4], o[4][4];
    #pragma unroll
    for (int i = 0; i < 4; i++) {
        m[i] = -1e30f; l[i] = 0.0f;
        #pragma unroll
        for (int j = 0; j < 4; j++) o[i][j] = 0.0f;
    }

    for (int jt = 0; jt <= qt; ++jt) {
        int k0 = jt * 64;
        __syncthreads();
        #pragma unroll
        for (int it = 0; it < 4; ++it) {
            int v = tid + 256 * it;
            int r = v >> 4, d4 = (v & 15) * 4;
            float4 kv = *(const float4*)&Kg[(size_t)(k0 + r) * D_ + d4];
            Kt[(d4 + 0) * 64 + r] = kv.x; Kt[(d4 + 1) * 64 + r] = kv.y;
            Kt[(d4 + 2) * 64 + r] = kv.z; Kt[(d4 + 3) * 64 + r] = kv.w;
            float4 vv = *(const float4*)&Vg[(size_t)(k0 + r) * D_ + d4];
            *(float4*)&Vs[r * 64 + d4] = vv;
        }
        __syncthreads();

        float s[4][4] = {};
        #pragma unroll 4
        for (int d = 0; d < 64; d++) {
            float4 av = *(float4*)&Qt[d * 64 + ty * 4];
            float4 bv = *(float4*)&Kt[d * 64 + tx * 4];
            float ar[4] = {av.x, av.y, av.z, av.w};
            float br[4] = {bv.x, bv.y, bv.z, bv.w};
            #pragma unroll
            for (int i = 0; i < 4; i++)
                #pragma unroll
                for (int j = 0; j < 4; j++)
                    s[i][j] = fmaf(ar[i], br[j], s[i][j]);
        }

        #pragma unroll
        for (int i = 0; i < 4; i++)
            #pragma unroll
            for (int j = 0; j < 4; j++) {
                s[i][j] *= 0.125f;
                if (jt == qt && (tx * 4 + j) > (ty * 4 + i)) s[i][j] = -1e30f;
            }

        #pragma unroll
        for (int i = 0; i < 4; i++) {
            float rm = fmaxf(fmaxf(s[i][0], s[i][1]), fmaxf(s[i][2], s[i][3]));
            #pragma unroll
            for (int off = 1; off < 16; off <<= 1)
                rm = fmaxf(rm, __shfl_xor_sync(0xffffffffu, rm, off));
            float mn = fmaxf(m[i], rm);
            float alpha = __expf(m[i] - mn);
            float rs = 0.0f;
            #pragma unroll
            for (int j = 0; j < 4; j++) { s[i][j] = __expf(s[i][j] - mn); rs += s[i][j]; }
            #pragma unroll
            for (int off = 1; off < 16; off <<= 1)
                rs += __shfl_xor_sync(0xffffffffu, rs, off);
            l[i] = l[i] * alpha + rs;
            m[i] = mn;
            #pragma unroll
            for (int j = 0; j < 4; j++) o[i][j] *= alpha;
        }

        __syncthreads();
        #pragma unroll
        for (int i = 0; i < 4; i++)
            *(float4*)&Kt[(ty * 4 + i) * 64 + tx * 4] =
                make_float4(s[i][0], s[i][1], s[i][2], s[i][3]);
        __syncthreads();

        #pragma unroll 2
        for (int c4 = 0; c4 < 64; c4 += 4) {
            float pr[4][4];
            #pragma unroll
            for (int i = 0; i < 4; i++) {
                float4 p4 = *(float4*)&Kt[(ty * 4 + i) * 64 + c4];
                pr[i][0] = p4.x; pr[i][1] = p4.y; pr[i][2] = p4.z; pr[i][3] = p4.w;
            }
            #pragma unroll
            for (int cc = 0; cc < 4; cc++) {
                float4 bv = *(float4*)&Vs[(c4 + cc) * 64 + tx * 4];
                float br[4] = {bv.x, bv.y, bv.z, bv.w};
                #pragma unroll
                for (int i = 0; i < 4; i++)
                    #pragma unroll
                    for (int j = 0; j < 4; j++)
                        o[i][j] = fmaf(pr[i][cc], br[j], o[i][j]);
            }
        }
    }

    int b = bh >> 4, h = bh & 15;
    #pragma unroll
    for (int i = 0; i < 4; i++) {
        int n = q0 + ty * 4 + i;
        float inv = 1.0f / l[i];
        size_t idx = ((size_t)b * N_ + n) * C_ + h * 64 + tx * 4;
        #pragma unroll
        for (int j = 0; j < 4; j++) {
            float v = o[i][j] * inv;
            __nv_bfloat16 hh = __float2bfloat16(v);
            __nv_bfloat16 ll = __float2bfloat16(v - __bfloat162float(hh));
            g_atth[idx + j] = hh;
            g_attl[idx + j] = ll;
        }
    }
}

// ---------------------------------------------------------------------------
extern "C" void kernel_launch(void* const* d_in, const int* in_sizes, int n_in,
                              void* d_out, int out_size)
{
    const float* x     = (const float*)d_in[0];
    // d_in[1] = attn_mask (exact additive causal mask; handled analytically)
    const float* Wqkv  = (const float*)d_in[2];
    const float* Wproj = (const float*)d_in[3];
    const float* bproj = (const float*)d_in[4];
    float* out = (float*)d_out;

    cudaFuncSetAttribute(hmma_qkv_kernel,
        cudaFuncAttributeMaxDynamicSharedMemorySize, SMEM_DYN);
    cudaFuncSetAttribute(hmma_proj_kernel,
        cudaFuncAttributeMaxDynamicSharedMemorySize, SMEM_DYN);

    __nv_bfloat16 *xh, *xl, *wqh, *wql, *wph, *wpl;
    cudaGetSymbolAddress((void**)&xh,  g_xh);
    cudaGetSymbolAddress((void**)&xl,  g_xl);
    cudaGetSymbolAddress((void**)&wqh, g_wqh);
    cudaGetSymbolAddress((void**)&wql, g_wql);
    cudaGetSymbolAddress((void**)&wph, g_wph);
    cudaGetSymbolAddress((void**)&wpl, g_wpl);

    int n4x = (B_*N_*C_) / 4;
    conv_split_kernel<<<(n4x + 255)/256, 256>>>(x, xh, xl, n4x);
    conv_T_kernel<<<dim3(3*C_/32, C_/32), 256>>>(Wqkv, wqh, wql, C_, 3*C_);
    conv_T_kernel<<<dim3(C_/32,   C_/32), 256>>>(Wproj, wph, wpl, C_, C_);

    hmma_qkv_kernel<<<dim3(3*C_/128, B_*N_/128), 256, SMEM_DYN>>>();

    attn_kernel<<<dim3(N_/64, BH_), 256>>>();

    hmma_proj_kernel<<<dim3(C_/128, B_*N_/128), 256, SMEM_DYN>>>(bproj, out);
}

// round 14
// speedup vs baseline: 3.1791x; 2.0152x over previous
#include <cuda_runtime.h>
#include <cuda_bf16.h>
#include <cstdint>
#include <math.h>

#define B_ 4
#define N_ 2048
#define C_ 1024
#define H_ 16
#define D_ 64
#define BH_ (B_*H_)

// ---------------- device scratch (allocation-free rule) ----------------
__device__ __nv_bfloat16 g_qh[(size_t)BH_*N_*D_];
__device__ __nv_bfloat16 g_ql[(size_t)BH_*N_*D_];
__device__ __nv_bfloat16 g_kh[(size_t)BH_*N_*D_];
__device__ __nv_bfloat16 g_kl[(size_t)BH_*N_*D_];
__device__ __nv_bfloat16 g_vh[(size_t)BH_*N_*D_];
__device__ __nv_bfloat16 g_vl[(size_t)BH_*N_*D_];
__device__ __nv_bfloat16 g_xh[(size_t)B_*N_*C_];
__device__ __nv_bfloat16 g_xl[(size_t)B_*N_*C_];
__device__ __nv_bfloat16 g_wqh[(size_t)3*C_*C_];   // W_qkv^T [3072][1024]
__device__ __nv_bfloat16 g_wql[(size_t)3*C_*C_];
__device__ __nv_bfloat16 g_wph[(size_t)C_*C_];     // W_proj^T [1024][1024]
__device__ __nv_bfloat16 g_wpl[(size_t)C_*C_];
__device__ __nv_bfloat16 g_atth[(size_t)B_*N_*C_];
__device__ __nv_bfloat16 g_attl[(size_t)B_*N_*C_];

// ---------------- helpers ----------------
__device__ __forceinline__ uint32_t smem_u32(const void* p) {
    uint32_t a;
    asm("{ .reg .u64 t; cvta.to.shared.u64 t, %1; cvt.u32.u64 %0, t; }"
        : "=r"(a) : "l"(p));
    return a;
}
#define CPA(dst, src) \
    asm volatile("cp.async.cg.shared.global [%0], [%1], 16;" \
                 :: "r"(dst), "l"(src) : "memory")
#define CP_COMMIT() asm volatile("cp.async.commit_group;" ::: "memory")
#define CP_WAIT0()  asm volatile("cp.async.wait_group 0;" ::: "memory")

__device__ __forceinline__ void ldsm4(uint32_t* r, uint32_t addr) {
    asm volatile("ldmatrix.sync.aligned.m8n8.x4.shared.b16 {%0,%1,%2,%3}, [%4];"
                 : "=r"(r[0]), "=r"(r[1]), "=r"(r[2]), "=r"(r[3]) : "r"(addr));
}
__device__ __forceinline__ void ldsm4t(uint32_t* r, uint32_t addr) {
    asm volatile("ldmatrix.sync.aligned.m8n8.x4.trans.shared.b16 {%0,%1,%2,%3}, [%4];"
                 : "=r"(r[0]), "=r"(r[1]), "=r"(r[2]), "=r"(r[3]) : "r"(addr));
}
__device__ __forceinline__ void mma16816(float* d, const uint32_t* a,
                                         uint32_t b0, uint32_t b1) {
    asm volatile(
        "mma.sync.aligned.m16n8k16.row.col.f32.bf16.bf16.f32 "
        "{%0,%1,%2,%3}, {%4,%5,%6,%7}, {%8,%9}, {%0,%1,%2,%3};"
        : "+f"(d[0]), "+f"(d[1]), "+f"(d[2]), "+f"(d[3])
        : "r"(a[0]), "r"(a[1]), "r"(a[2]), "r"(a[3]), "r"(b0), "r"(b1));
}
__device__ __forceinline__ void split2(float a, float b, uint32_t& hi, uint32_t& lo) {
    __nv_bfloat16 ha = __float2bfloat16(a), hb = __float2bfloat16(b);
    __nv_bfloat16 la = __float2bfloat16(a - __bfloat162float(ha));
    __nv_bfloat16 lb = __float2bfloat16(b - __bfloat162float(hb));
    __nv_bfloat162 Hh; Hh.x = ha; Hh.y = hb; hi = *(uint32_t*)&Hh;
    __nv_bfloat162 Ll; Ll.x = la; Ll.y = lb; lo = *(uint32_t*)&Ll;
}
__device__ __forceinline__ void wr_split(__nv_bfloat16* dh, __nv_bfloat16* dl,
                                         size_t idx, float a, float b) {
    uint32_t hi, lo;
    split2(a, b, hi, lo);
    *(uint32_t*)(dh + idx) = hi;
    *(uint32_t*)(dl + idx) = lo;
}

// GEMM smem: 2 stages x 4 tiles (Ah, Al, Bh, Bl), each 128 rows x 128B, SW128
#define SOFF(s, w) (((s)*4 + (w)) * 16384)
#define SMEM_DYN (8 * 16384)

// ---------------------------------------------------------------------------
// HMMA split-3 GEMM mainloop (proven R11)
// ---------------------------------------------------------------------------
__device__ __forceinline__ void hmma_tile(
    const __nv_bfloat16* __restrict__ Ah, const __nv_bfloat16* __restrict__ Al,
    const __nv_bfloat16* __restrict__ Bh, const __nv_bfloat16* __restrict__ Bl,
    int m0, int n0, char* smem, float acc[4][4][4])
{
    const int NC = 16;
    uint32_t sb = smem_u32(smem);
    int tid = threadIdx.x, lane = tid & 31;
    int wm = (tid >> 5) & 1, wn = tid >> 6;

    int rr[4]; int koB[4]; uint32_t soff[4];
    #pragma unroll
    for (int i = 0; i < 4; i++) {
        int e = tid + 256 * i;
        rr[i] = e >> 3; koB[i] = (e & 7) * 16;
        soff[i] = (uint32_t)(rr[i] * 128 + (koB[i] ^ ((rr[i] & 7) << 4)));
    }

    int lr = lane & 15;
    uint32_t ch16 = (uint32_t)((lane >> 4) * 16);
    uint32_t arow[4], xa[4], brow[2], xb[2];
    #pragma unroll
    for (int mt = 0; mt < 4; mt++) {
        int r = wm * 64 + mt * 16 + lr;
        arow[mt] = (uint32_t)(r * 128); xa[mt] = (uint32_t)((r & 7) << 4);
    }
    #pragma unroll
    for (int p = 0; p < 2; p++) {
        int r = wn * 32 + p * 16 + lr;
        brow[p] = (uint32_t)(r * 128); xb[p] = (uint32_t)((r & 7) << 4);
    }

    #define STAGE(c, s) {                                                      \
        int k0b = (c) * 128;                                                   \
        _Pragma("unroll") for (int i = 0; i < 4; i++) {                        \
            const char* asrc = (const char*)Ah + (size_t)(m0 + rr[i])*2048 + k0b + koB[i]; \
            const char* lsrc = (const char*)Al + (size_t)(m0 + rr[i])*2048 + k0b + koB[i]; \
            const char* bsrc = (const char*)Bh + (size_t)(n0 + rr[i])*2048 + k0b + koB[i]; \
            const char* csrc = (const char*)Bl + (size_t)(n0 + rr[i])*2048 + k0b + koB[i]; \
            CPA(sb + SOFF(s,0) + soff[i], asrc);                               \
            CPA(sb + SOFF(s,1) + soff[i], lsrc);                               \
            CPA(sb + SOFF(s,2) + soff[i], bsrc);                               \
            CPA(sb + SOFF(s,3) + soff[i], csrc); } }

    STAGE(0, 0); CP_COMMIT(); CP_WAIT0();
    __syncthreads();

    for (int c = 0; c < NC; c++) {
        int s = c & 1;
        if (c + 1 < NC) { STAGE(c + 1, (c + 1) & 1); CP_COMMIT(); }

        uint32_t bAh = sb + SOFF(s, 0), bAl = sb + SOFF(s, 1);
        uint32_t bBh = sb + SOFF(s, 2), bBl = sb + SOFF(s, 3);
        #pragma unroll
        for (int ks = 0; ks < 4; ks++) {
            uint32_t ka = (uint32_t)(ks * 32) + ch16;
            uint32_t fah[4][4], fal[4][4], fbh[2][4], fbl[2][4];
            #pragma unroll
            for (int mt = 0; mt < 4; mt++) {
                ldsm4(fah[mt], bAh + arow[mt] + (ka ^ xa[mt]));
                ldsm4(fal[mt], bAl + arow[mt] + (ka ^ xa[mt]));
            }
            #pragma unroll
            for (int p = 0; p < 2; p++) {
                ldsm4(fbh[p], bBh + brow[p] + (ka ^ xb[p]));
                ldsm4(fbl[p], bBl + brow[p] + (ka ^ xb[p]));
            }
            #pragma unroll
            for (int mt = 0; mt < 4; mt++)
                #pragma unroll
                for (int nt = 0; nt < 4; nt++) {
                    int p = nt >> 1, o = nt & 1;
                    mma16816(acc[mt][nt], fah[mt], fbh[p][o], fbh[p][o + 2]);
                    mma16816(acc[mt][nt], fah[mt], fbl[p][o], fbl[p][o + 2]);
                    mma16816(acc[mt][nt], fal[mt], fbh[p][o], fbh[p][o + 2]);
                }
        }
        if (c + 1 < NC) CP_WAIT0();
        __syncthreads();
    }
    #undef STAGE
}

// ---------------------------------------------------------------------------
// QKV GEMM -> bf16-split q/k/v [BH][N][64] (q pre-scaled by 0.125)
// ---------------------------------------------------------------------------
__global__ __launch_bounds__(256, 1) void hmma_qkv_kernel() {
    extern __shared__ char dsm[];
    int m0 = blockIdx.y * 128, n0 = blockIdx.x * 128;
    float acc[4][4][4] = {};
    hmma_tile(g_xh, g_xl, g_wqh, g_wql, m0, n0, dsm, acc);

    int lane = threadIdx.x & 31;
    int wm = (threadIdx.x >> 5) & 1, wn = threadIdx.x >> 6;
    int g = lane >> 2, tg = lane & 3;
    #pragma unroll
    for (int mt = 0; mt < 4; mt++)
        #pragma unroll
        for (int nt = 0; nt < 4; nt++) {
            int m = m0 + wm * 64 + mt * 16 + g;
            int n = n0 + wn * 32 + nt * 8 + tg * 2;
            int which = n >> 10, h = (n >> 6) & 15, d = n & 63;
            __nv_bfloat16 *dh, *dl;
            float sc;
            if (which == 0)      { dh = g_qh; dl = g_ql; sc = 0.125f; }
            else if (which == 1) { dh = g_kh; dl = g_kl; sc = 1.0f; }
            else                 { dh = g_vh; dl = g_vl; sc = 1.0f; }
            int b = m >> 11, nn = m & (N_ - 1);
            size_t base = (((size_t)(b * H_ + h)) * N_ + nn) * D_ + d;
            wr_split(dh, dl, base,          acc[mt][nt][0] * sc, acc[mt][nt][1] * sc);
            wr_split(dh, dl, base + 8 * D_, acc[mt][nt][2] * sc, acc[mt][nt][3] * sc);
        }
}

// ---------------------------------------------------------------------------
// proj GEMM + bias -> out (unchanged, proven)
// ---------------------------------------------------------------------------
__global__ __launch_bounds__(256, 1) void hmma_proj_kernel(
    const float* __restrict__ bias, float* __restrict__ out) {
    extern __shared__ char dsm[];
    int m0 = blockIdx.y * 128, n0 = blockIdx.x * 128;
    float acc[4][4][4] = {};
    hmma_tile(g_atth, g_attl, g_wph, g_wpl, m0, n0, dsm, acc);

    int lane = threadIdx.x & 31;
    int wm = (threadIdx.x >> 5) & 1, wn = threadIdx.x >> 6;
    int g = lane >> 2, tg = lane & 3;
    #pragma unroll
    for (int mt = 0; mt < 4; mt++)
        #pragma unroll
        for (int nt = 0; nt < 4; nt++) {
            int m = m0 + wm * 64 + mt * 16 + g;
            int n = n0 + wn * 32 + nt * 8 + tg * 2;
            float b0 = bias[n], b1 = bias[n + 1];
            *(float2*)&out[(size_t)m * C_ + n] =
                make_float2(acc[mt][nt][0] + b0, acc[mt][nt][1] + b1);
            *(float2*)&out[(size_t)(m + 8) * C_ + n] =
                make_float2(acc[mt][nt][2] + b0, acc[mt][nt][3] + b1);
        }
}

// ---------------------------------------------------------------------------
// Conversion kernels (unchanged)
// ---------------------------------------------------------------------------
__global__ __launch_bounds__(256) void conv_split_kernel(
    const float* __restrict__ in, __nv_bfloat16* __restrict__ oh,
    __nv_bfloat16* __restrict__ ol, int n4) {
    int i = blockIdx.x * 256 + threadIdx.x;
    if (i >= n4) return;
    float4 v = ((const float4*)in)[i];
    float vv[4] = {v.x, v.y, v.z, v.w};
    __nv_bfloat162 h2[2], l2[2];
    #pragma unroll
    for (int j = 0; j < 4; j++) {
        __nv_bfloat16 h = __float2bfloat16(vv[j]);
        __nv_bfloat16 l = __float2bfloat16(vv[j] - __bfloat162float(h));
        ((__nv_bfloat16*)h2)[j] = h;
        ((__nv_bfloat16*)l2)[j] = l;
    }
    ((__nv_bfloat162*)oh)[i*2]   = h2[0]; ((__nv_bfloat162*)oh)[i*2+1] = h2[1];
    ((__nv_bfloat162*)ol)[i*2]   = l2[0]; ((__nv_bfloat162*)ol)[i*2+1] = l2[1];
}

__global__ __launch_bounds__(256) void conv_T_kernel(
    const float* __restrict__ W, __nv_bfloat16* __restrict__ oh,
    __nv_bfloat16* __restrict__ ol, int K, int Nw) {
    __shared__ float t[32][33];
    int n0 = blockIdx.x * 32, k0 = blockIdx.y * 32;
    int tx = threadIdx.x & 31, ty = threadIdx.x >> 5;
    #pragma unroll
    for (int p = 0; p < 32; p += 8)
        t[ty + p][tx] = W[(size_t)(k0 + ty + p)*Nw + n0 + tx];
    __syncthreads();
    #pragma unroll
    for (int p = 0; p < 32; p += 8) {
        float v = t[tx][ty + p];
        __nv_bfloat16 h = __float2bfloat16(v);
        __nv_bfloat16 l = __float2bfloat16(v - __bfloat162float(h));
        size_t o = (size_t)(n0 + ty + p)*K + k0 + tx;
        oh[o] = h; ol[o] = l;
    }
}

// ---------------------------------------------------------------------------
// HMMA flash attention. Block = 128 q-rows x one (b,h). 8 warps x m16.
// S = QK^T split-3; softmax on fragments; P repacked in regs; PV split-2.
// smem: 2 stages x {Kh,Kl,Vh,Vl} x 8KB = 64KB (Q staged through stage0 first)
// ---------------------------------------------------------------------------
#define ASOFF(s, w) (((s)*4 + (w)) * 8192)
#define ASMEM_DYN 65536

__global__ __launch_bounds__(256, 1) void fmha_kernel() {
    extern __shared__ char dsm[];
    uint32_t sb = smem_u32(dsm);
    int tid = threadIdx.x, lane = tid & 31, w = tid >> 5;
    int qtb = blockIdx.x, bh = blockIdx.y;
    int q0 = qtb * 128;
    int g = lane >> 2, tg = lane & 3;
    int lr = lane & 15;
    uint32_t ch16 = (uint32_t)((lane >> 4) * 16);

    const char* Qh = (const char*)g_qh + (size_t)bh * N_ * 128;
    const char* Ql = (const char*)g_ql + (size_t)bh * N_ * 128;
    const char* Kh = (const char*)g_kh + (size_t)bh * N_ * 128;
    const char* Kl = (const char*)g_kl + (size_t)bh * N_ * 128;
    const char* Vh = (const char*)g_vh + (size_t)bh * N_ * 128;
    const char* Vl = (const char*)g_vl + (size_t)bh * N_ * 128;

    // --- load Q tile (128 rows x 128B, hi/lo) into stage0 region ---
    #pragma unroll
    for (int i = 0; i < 4; i++) {
        int e = tid + 256 * i;
        int row = e >> 3;
        uint32_t sl = (uint32_t)((e & 7) * 16);
        uint32_t off = (uint32_t)(row * 128) + (sl ^ (uint32_t)((row & 7) << 4));
        size_t sByte = (size_t)(q0 + row) * 128 + sl;
        CPA(sb + off,          Qh + sByte);
        CPA(sb + 16384 + off,  Ql + sByte);
    }
    CP_COMMIT(); CP_WAIT0();
    __syncthreads();

    // --- Q fragments (m16 x k64, hi/lo) ---
    uint32_t qh[4][4], ql[4][4];
    {
        int r = w * 16 + lr;
        uint32_t ar = (uint32_t)(r * 128), xa = (uint32_t)((r & 7) << 4);
        #pragma unroll
        for (int ks = 0; ks < 4; ks++) {
            uint32_t ka = (uint32_t)(ks * 32) + ch16;
            ldsm4(qh[ks], sb + ar + (ka ^ xa));
            ldsm4(ql[ks], sb + 16384 + ar + (ka ^ xa));
        }
    }
    __syncthreads();   // Q consumed; stage0 may be overwritten

    float o[8][4];
    #pragma unroll
    for (int j = 0; j < 8; j++)
        #pragma unroll
        for (int c = 0; c < 4; c++) o[j][c] = 0.0f;
    float m0 = -1e30f, m1 = -1e30f, l0 = 0.0f, l1 = 0.0f;

    int jmax = 2 * qtb + 1;

    #define KVST(jt, st) {                                                     \
        _Pragma("unroll") for (int i = 0; i < 2; i++) {                        \
            int e = tid + 256 * i;                                             \
            int row = e >> 3;                                                  \
            uint32_t sl = (uint32_t)((e & 7) * 16);                            \
            uint32_t off = (uint32_t)(row * 128) + (sl ^ (uint32_t)((row & 7) << 4)); \
            size_t sByte = (size_t)((jt) * 64 + row) * 128 + sl;               \
            CPA(sb + ASOFF(st, 0) + off, Kh + sByte);                          \
            CPA(sb + ASOFF(st, 1) + off, Kl + sByte);                          \
            CPA(sb + ASOFF(st, 2) + off, Vh + sByte);                          \
            CPA(sb + ASOFF(st, 3) + off, Vl + sByte); } }

    KVST(0, 0); CP_COMMIT(); CP_WAIT0();
    __syncthreads();

    for (int jt = 0; jt <= jmax; jt++) {
        int st = jt & 1;
        if (jt < jmax) { KVST(jt + 1, st ^ 1); CP_COMMIT(); }

        // ---- S = Q K^T (split-3) ----
        float s[8][4];
        #pragma unroll
        for (int j = 0; j < 8; j++)
            #pragma unroll
            for (int c = 0; c < 4; c++) s[j][c] = 0.0f;

        uint32_t kbH = sb + ASOFF(st, 0), kbL = sb + ASOFF(st, 1);
        #pragma unroll
        for (int ks = 0; ks < 4; ks++) {
            uint32_t ka = (uint32_t)(ks * 32) + ch16;
            uint32_t fbh[4][4], fbl[4][4];
            #pragma unroll
            for (int p = 0; p < 4; p++) {
                int r = p * 16 + lr;
                uint32_t br = (uint32_t)(r * 128), xb = (uint32_t)((r & 7) << 4);
                ldsm4(fbh[p], kbH + br + (ka ^ xb));
                ldsm4(fbl[p], kbL + br + (ka ^ xb));
            }
            #pragma unroll
            for (int j = 0; j < 8; j++) {
                int p = j >> 1, oo = j & 1;
                mma16816(s[j], qh[ks], fbh[p][oo], fbh[p][oo + 2]);
                mma16816(s[j], qh[ks], fbl[p][oo], fbl[p][oo + 2]);
                mma16816(s[j], ql[ks], fbh[p][oo], fbh[p][oo + 2]);
            }
        }

        // ---- causal mask (diagonal region only) ----
        if (jt >= 2 * qtb) {
            int row0 = q0 + w * 16 + g, row1 = row0 + 8;
            #pragma unroll
            for (int j = 0; j < 8; j++) {
                int col = jt * 64 + 8 * j + 2 * tg;
                if (col > row0)     s[j][0] = -1e30f;
                if (col + 1 > row0) s[j][1] = -1e30f;
                if (col > row1)     s[j][2] = -1e30f;
                if (col + 1 > row1) s[j][3] = -1e30f;
            }
        }

        // ---- online softmax (rows g and g+8; quad reduce over tg) ----
        float mx0 = -1e30f, mx1 = -1e30f;
        #pragma unroll
        for (int j = 0; j < 8; j++) {
            mx0 = fmaxf(mx0, fmaxf(s[j][0], s[j][1]));
            mx1 = fmaxf(mx1, fmaxf(s[j][2], s[j][3]));
        }
        mx0 = fmaxf(mx0, __shfl_xor_sync(0xffffffffu, mx0, 1));
        mx0 = fmaxf(mx0, __shfl_xor_sync(0xffffffffu, mx0, 2));
        mx1 = fmaxf(mx1, __shfl_xor_sync(0xffffffffu, mx1, 1));
        mx1 = fmaxf(mx1, __shfl_xor_sync(0xffffffffu, mx1, 2));
        float m0n = fmaxf(m0, mx0), m1n = fmaxf(m1, mx1);
        float a0 = __expf(m0 - m0n), a1 = __expf(m1 - m1n);
        float rs0 = 0.0f, rs1 = 0.0f;
        #pragma unroll
        for (int j = 0; j < 8; j++) {
            s[j][0] = __expf(s[j][0] - m0n);
            s[j][1] = __expf(s[j][1] - m0n);
            s[j][2] = __expf(s[j][2] - m1n);
            s[j][3] = __expf(s[j][3] - m1n);
            rs0 += s[j][0] + s[j][1];
            rs1 += s[j][2] + s[j][3];
        }
        rs0 += __shfl_xor_sync(0xffffffffu, rs0, 1);
        rs0 += __shfl_xor_sync(0xffffffffu, rs0, 2);
        rs1 += __shfl_xor_sync(0xffffffffu, rs1, 1);
        rs1 += __shfl_xor_sync(0xffffffffu, rs1, 2);
        l0 = l0 * a0 + rs0; l1 = l1 * a1 + rs1;
        m0 = m0n; m1 = m1n;
        #pragma unroll
        for (int j = 0; j < 8; j++) {
            o[j][0] *= a0; o[j][1] *= a0;
            o[j][2] *= a1; o[j][3] *= a1;
        }

        // ---- P -> A-fragments (split-2), pure register repack ----
        uint32_t pah[4][4], pal[4][4];
        #pragma unroll
        for (int ks = 0; ks < 4; ks++) {
            split2(s[2*ks][0],   s[2*ks][1],   pah[ks][0], pal[ks][0]);
            split2(s[2*ks][2],   s[2*ks][3],   pah[ks][1], pal[ks][1]);
            split2(s[2*ks+1][0], s[2*ks+1][1], pah[ks][2], pal[ks][2]);
            split2(s[2*ks+1][2], s[2*ks+1][3], pah[ks][3], pal[ks][3]);
        }

        // ---- O += P V (split-2, V via ldmatrix.trans) ----
        uint32_t vbHB = sb + ASOFF(st, 2), vbLB = sb + ASOFF(st, 3);
        int vr = (lane & 7) + 8 * ((lane >> 3) & 1);
        uint32_t vx = (uint32_t)(16 * (lane >> 4));
        #pragma unroll
        for (int ks = 0; ks < 4; ks++) {
            int row = ks * 16 + vr;
            uint32_t rB = (uint32_t)(row * 128), xw = (uint32_t)((row & 7) << 4);
            uint32_t vbh[4][4], vbl[4][4];
            #pragma unroll
            for (int c = 0; c < 4; c++) {
                uint32_t x = (uint32_t)(32 * c) + vx;
                ldsm4t(vbh[c], vbHB + rB + (x ^ xw));
                ldsm4t(vbl[c], vbLB + rB + (x ^ xw));
            }
            #pragma unroll
            for (int j = 0; j < 8; j++) {
                int c = j >> 1, oo = j & 1;
                mma16816(o[j], pah[ks], vbh[c][2*oo], vbh[c][2*oo + 1]);
                mma16816(o[j], pah[ks], vbl[c][2*oo], vbl[c][2*oo + 1]);
                mma16816(o[j], pal[ks], vbh[c][2*oo], vbh[c][2*oo + 1]);
            }
        }

        if (jt < jmax) CP_WAIT0();
        __syncthreads();
    }
    #undef KVST

    // ---- epilogue: O/l -> bf16-split attention output [b][n][h*64+d] ----
    float i0 = 1.0f / l0, i1 = 1.0f / l1;
    int b = bh >> 4, h = bh & 15;
    int r0 = q0 + w * 16 + g, r1 = r0 + 8;
    #pragma unroll
    for (int j = 0; j < 8; j++) {
        int d = 8 * j + 2 * tg;
        size_t i0x = ((size_t)b * N_ + r0) * C_ + h * 64 + d;
        size_t i1x = ((size_t)b * N_ + r1) * C_ + h * 64 + d;
        wr_split(g_atth, g_attl, i0x, o[j][0] * i0, o[j][1] * i0);
        wr_split(g_atth, g_attl, i1x, o[j][2] * i1, o[j][3] * i1);
    }
}

// ---------------------------------------------------------------------------
extern "C" void kernel_launch(void* const* d_in, const int* in_sizes, int n_in,
                              void* d_out, int out_size)
{
    const float* x     = (const float*)d_in[0];
    // d_in[1] = attn_mask (exact additive causal mask; handled analytically)
    const float* Wqkv  = (const float*)d_in[2];
    const float* Wproj = (const float*)d_in[3];
    const float* bproj = (const float*)d_in[4];
    float* out = (float*)d_out;

    cudaFuncSetAttribute(hmma_qkv_kernel,
        cudaFuncAttributeMaxDynamicSharedMemorySize, SMEM_DYN);
    cudaFuncSetAttribute(hmma_proj_kernel,
        cudaFuncAttributeMaxDynamicSharedMemorySize, SMEM_DYN);
    cudaFuncSetAttribute(fmha_kernel,
        cudaFuncAttributeMaxDynamicSharedMemorySize, ASMEM_DYN);

    __nv_bfloat16 *xh, *xl, *wqh, *wql, *wph, *wpl;
    cudaGetSymbolAddress((void**)&xh,  g_xh);
    cudaGetSymbolAddress((void**)&xl,  g_xl);
    cudaGetSymbolAddress((void**)&wqh, g_wqh);
    cudaGetSymbolAddress((void**)&wql, g_wql);
    cudaGetSymbolAddress((void**)&wph, g_wph);
    cudaGetSymbolAddress((void**)&wpl, g_wpl);

    int n4x = (B_*N_*C_) / 4;
    conv_split_kernel<<<(n4x + 255)/256, 256>>>(x, xh, xl, n4x);
    conv_T_kernel<<<dim3(3*C_/32, C_/32), 256>>>(Wqkv, wqh, wql, C_, 3*C_);
    conv_T_kernel<<<dim3(C_/32,   C_/32), 256>>>(Wproj, wph, wpl, C_, C_);

    hmma_qkv_kernel<<<dim3(3*C_/128, B_*N_/128), 256, SMEM_DYN>>>();

    fmha_kernel<<<dim3(N_/128, BH_), 256, ASMEM_DYN>>>();

    hmma_proj_kernel<<<dim3(C_/128, B_*N_/128), 256, SMEM_DYN>>>(bproj, out);
}